// round 15
// baseline (speedup 1.0000x reference)
#include <cuda_runtime.h>
#include <cuda_fp16.h>

#define DEV_INLINE __device__ __forceinline__

constexpr int NN   = 1024;
constexpr int EE   = 65536;
constexpr int E2   = EE + NN;      // edges + self loops
constexpr int W1O  = 512;          // H*256
constexpr int C1   = 256;
constexpr int W2O  = 128;          // H*64
constexpr int C2   = 64;

// ---------------- scratch (device globals) -------------
__device__ __half g_xph[2][NN * W1O];   // layer-1 projected features (fp16)
__device__ float  g_bb[W1O];            // b1_0+b1_1
__device__ float  g_cbias[1];           // sum((b2_0+b2_1)*wlin)
__device__ float  g_att[2 * 2 * NN * 2];// layer1 [rel][als/ald][node*2+head]
__device__ float  g_V[2][6][W1O];       // W2_r @ {as2_h0,as2_h1,ad2_h0,ad2_h1,wl_h0,wl_h1}
__device__ float  g_l2[2][3][NN * 2];   // [rel][als2/ald2/q][node*2+head]
__device__ int    g_cnt4[4][2][NN];     // sharded edge counts
__device__ int    g_cur4[4][2][NN];     // sharded fill cursors
__device__ int    g_off[2][NN + 1];
__device__ int    g_srcs[2][E2];
__device__ float  g_s2[2][NN];          // per-relation score partials
__device__ int    g_flag;               // scan-done flag

// =======================================================================
// FUSED: gemm1 (both relations, fp16 out) + attn1 logits + sharded count
//        + layer-2 projection-vector prep (4 extra blocks)
// =======================================================================
constexpr int G1_GEMM_BLOCKS  = (W1O / 64) * (NN / 128) * 2;   // 128
constexpr int G1_COUNT_BLOCKS = EE / 4 / 256;                  // 64
constexpr int G1_PREP_BLOCKS  = 4;                             // 2 rel x 2 halves

__global__ void __launch_bounds__(256)
k_gemm1_count(const float* __restrict__ A,
              const float* __restrict__ B0, const float* __restrict__ B1,
              __half* __restrict__ Ch0, __half* __restrict__ Ch1,
              const int* __restrict__ ei0, const int* __restrict__ ei1,
              const float* __restrict__ as0, const float* __restrict__ as1,
              const float* __restrict__ ad0, const float* __restrict__ ad1,
              float* __restrict__ att,
              const float* __restrict__ W2_0, const float* __restrict__ W2_1,
              const float* __restrict__ as2_0, const float* __restrict__ as2_1,
              const float* __restrict__ ad2_0, const float* __restrict__ ad2_1,
              const float* __restrict__ wlin) {
    int bid = blockIdx.x;
    int t = threadIdx.x;

    if (bid >= G1_GEMM_BLOCKS + G1_COUNT_BLOCKS) {
        // ---- prep: V[rel][v][k] = dot64(W2_r[k, h*64:...], u_h) ----
        int pb  = bid - (G1_GEMM_BLOCKS + G1_COUNT_BLOCKS);   // 0..3
        int rel = pb >> 1, half = pb & 1;
        int k = half * 256 + t;                               // W2 row
        const float* W2r = rel ? W2_1 : W2_0;
        const float* a2  = rel ? as2_1 : as2_0;               // [2][64]
        const float* d2  = rel ? ad2_1 : ad2_0;
        const float* row = W2r + (size_t)k * W2O;
        float s_[6] = {0.f, 0.f, 0.f, 0.f, 0.f, 0.f};
        #pragma unroll 8
        for (int c = 0; c < 64; c++) {
            float w0 = row[c], w1 = row[64 + c];
            s_[0] = fmaf(w0, a2[c],        s_[0]);
            s_[1] = fmaf(w1, a2[64 + c],   s_[1]);
            s_[2] = fmaf(w0, d2[c],        s_[2]);
            s_[3] = fmaf(w1, d2[64 + c],   s_[3]);
            s_[4] = fmaf(w0, wlin[c],      s_[4]);
            s_[5] = fmaf(w1, wlin[64 + c], s_[5]);
        }
        #pragma unroll
        for (int v = 0; v < 6; v++) g_V[rel][v][k] = s_[v];
        return;
    }

    if (bid >= G1_GEMM_BLOCKS) {
        if (bid == G1_GEMM_BLOCKS && t == 0) g_flag = 0;   // reset for scanfill
        int cid = bid - G1_GEMM_BLOCKS;
        int idx = cid * 256 + t;
        int4 d0 = ((const int4*)(ei0 + EE))[idx];
        int4 d1 = ((const int4*)(ei1 + EE))[idx];
        atomicAdd(&g_cnt4[0][0][d0.x], 1); atomicAdd(&g_cnt4[1][0][d0.y], 1);
        atomicAdd(&g_cnt4[2][0][d0.z], 1); atomicAdd(&g_cnt4[3][0][d0.w], 1);
        atomicAdd(&g_cnt4[0][1][d1.x], 1); atomicAdd(&g_cnt4[1][1][d1.y], 1);
        atomicAdd(&g_cnt4[2][1][d1.z], 1); atomicAdd(&g_cnt4[3][1][d1.w], 1);
        return;
    }

    constexpr int K = 256, Nc = W1O;
    __shared__ float4 sh[768];
    float*  As  = (float*)sh;
    float4* As4 = sh;                            // row stride 32
    float4* Bs4 = sh + 512;                      // [16][16]

    int rel = bid >> 6;
    int r   = bid & 63;
    int bn  = (r & 7) * 64;
    int bm  = (r >> 3) * 128;
    const float* B = rel ? B1 : B0;
    __half*      Ch = rel ? Ch1 : Ch0;

    int tx = t & 15, ty = t >> 4;
    int am = t >> 2, ak = (t & 3) * 4;

    float4 acc[8];
    #pragma unroll
    for (int i = 0; i < 8; i++) acc[i] = make_float4(0.f, 0.f, 0.f, 0.f);

    float4 a_reg0 = *(const float4*)(A + (size_t)(bm + am) * K + ak);
    float4 a_reg1 = *(const float4*)(A + (size_t)(bm + am + 64) * K + ak);
    float4 b_reg  = *(const float4*)(B + (size_t)(t >> 4) * Nc + bn + (t & 15) * 4);

    for (int k0 = 0; k0 < K; k0 += 16) {
        As[(ak + 0) * 128 + am] = a_reg0.x;
        As[(ak + 1) * 128 + am] = a_reg0.y;
        As[(ak + 2) * 128 + am] = a_reg0.z;
        As[(ak + 3) * 128 + am] = a_reg0.w;
        As[(ak + 0) * 128 + am + 64] = a_reg1.x;
        As[(ak + 1) * 128 + am + 64] = a_reg1.y;
        As[(ak + 2) * 128 + am + 64] = a_reg1.z;
        As[(ak + 3) * 128 + am + 64] = a_reg1.w;
        Bs4[(t >> 4) * 16 + (t & 15)] = b_reg;
        __syncthreads();

        if (k0 + 16 < K) {
            a_reg0 = *(const float4*)(A + (size_t)(bm + am) * K + k0 + 16 + ak);
            a_reg1 = *(const float4*)(A + (size_t)(bm + am + 64) * K + k0 + 16 + ak);
            b_reg  = *(const float4*)(B + (size_t)(k0 + 16 + (t >> 4)) * Nc + bn + (t & 15) * 4);
        }

        #pragma unroll
        for (int k = 0; k < 16; k++) {
            float4 a0 = As4[k * 32 + ty * 2];
            float4 a1 = As4[k * 32 + ty * 2 + 1];
            float4 b  = Bs4[k * 16 + tx];
            float ar[8] = {a0.x, a0.y, a0.z, a0.w, a1.x, a1.y, a1.z, a1.w};
            #pragma unroll
            for (int i = 0; i < 8; i++) {
                acc[i].x = fmaf(ar[i], b.x, acc[i].x);
                acc[i].y = fmaf(ar[i], b.y, acc[i].y);
                acc[i].z = fmaf(ar[i], b.z, acc[i].z);
                acc[i].w = fmaf(ar[i], b.w, acc[i].w);
            }
        }
        __syncthreads();
    }
    #pragma unroll
    for (int i = 0; i < 8; i++) {
        __half2 h01 = __floats2half2_rn(acc[i].x, acc[i].y);
        __half2 h23 = __floats2half2_rn(acc[i].z, acc[i].w);
        uint2 v;
        v.x = *reinterpret_cast<unsigned*>(&h01);
        v.y = *reinterpret_cast<unsigned*>(&h23);
        ((uint2*)(Ch + (size_t)(bm + ty * 8 + i) * Nc))[(bn >> 2) + tx] = v;
    }

    // fused attn1 logit partials
    const float* asrc = rel ? as1 : as0;
    const float* adst = rel ? ad1 : ad0;
    int h   = bn >> 8;
    int cin = (bn & 255) + tx * 4;
    float4 avs = *(const float4*)(asrc + h * C1 + cin);
    float4 avd = *(const float4*)(adst + h * C1 + cin);
    float* alsb = att + (rel * 2 + 0) * (NN * 2);
    float* aldb = att + (rel * 2 + 1) * (NN * 2);
    #pragma unroll
    for (int i = 0; i < 8; i++) {
        float ps = acc[i].x * avs.x + acc[i].y * avs.y + acc[i].z * avs.z + acc[i].w * avs.w;
        float pd = acc[i].x * avd.x + acc[i].y * avd.y + acc[i].z * avd.z + acc[i].w * avd.w;
        #pragma unroll
        for (int o = 8; o; o >>= 1) {
            ps += __shfl_xor_sync(0xffffffffu, ps, o);
            pd += __shfl_xor_sync(0xffffffffu, pd, o);
        }
        if (tx == 0) {
            int row = bm + ty * 8 + i;
            atomicAdd(&alsb[row * 2 + h], ps);
            atomicAdd(&aldb[row * 2 + h], pd);
        }
    }
}

// =======================================================================
// FUSED scan (blocks 0,1) + fill (blocks 2..18), flag-synchronized
// =======================================================================
constexpr int SF_FILL_BLOCKS = 17;

__global__ void __launch_bounds__(1024)
k_scanfill(const int* __restrict__ ei0, const int* __restrict__ ei1,
           const float* __restrict__ b1_0, const float* __restrict__ b1_1,
           const float* __restrict__ b2_0, const float* __restrict__ b2_1,
           const float* __restrict__ wlin) {
    int b = blockIdx.x;
    int t = threadIdx.x;

    if (b < 2) {
        int r = b;
        __shared__ int sh[NN];
        __shared__ float fred[4];

        int c0 = g_cnt4[0][r][t] + 1;   // self loop in shard 0
        int c1 = g_cnt4[1][r][t];
        int c2 = g_cnt4[2][r][t];
        int c3 = g_cnt4[3][r][t];
        int mine = c0 + c1 + c2 + c3;
        sh[t] = mine;
        __syncthreads();
        #pragma unroll
        for (int d = 1; d < NN; d <<= 1) {
            int v = (t >= d) ? sh[t - d] : 0;
            __syncthreads();
            sh[t] += v;
            __syncthreads();
        }
        g_off[r][t + 1] = sh[t];
        if (t == 0) g_off[r][0] = 0;
        int base = sh[t] - mine;
        g_cur4[0][r][t] = base;
        g_cur4[1][r][t] = base + c0;
        g_cur4[2][r][t] = base + c0 + c1;
        g_cur4[3][r][t] = base + c0 + c1 + c2;

        if (r == 0) {
            if (t < W1O) g_bb[t] = b1_0[t] + b1_1[t];
        } else {
            float p = 0.f;
            if (t < W2O) p = (b2_0[t] + b2_1[t]) * wlin[t];
            if (t < 128) {
                #pragma unroll
                for (int o = 16; o; o >>= 1) p += __shfl_xor_sync(0xffffffffu, p, o);
                if ((t & 31) == 0) fred[t >> 5] = p;
            }
            __syncthreads();
            if (t == 0) g_cbias[0] = fred[0] + fred[1] + fred[2] + fred[3];
        }

        __threadfence();
        __syncthreads();
        if (t == 0) atomicAdd(&g_flag, 1);
        return;
    }

    if (t == 0) {
        while (atomicAdd(&g_flag, 0) < 2) {}
    }
    __syncthreads();
    __threadfence();

    int fb = b - 2;
    if (fb < 16) {
        int idx = fb * 1024 + t;
        int4 s0 = ((const int4*)ei0)[idx];
        int4 d0 = ((const int4*)(ei0 + EE))[idx];
        int4 s1 = ((const int4*)ei1)[idx];
        int4 d1 = ((const int4*)(ei1 + EE))[idx];
        int p;
        p = atomicAdd(&g_cur4[0][0][d0.x], 1); g_srcs[0][p] = s0.x;
        p = atomicAdd(&g_cur4[1][0][d0.y], 1); g_srcs[0][p] = s0.y;
        p = atomicAdd(&g_cur4[2][0][d0.z], 1); g_srcs[0][p] = s0.z;
        p = atomicAdd(&g_cur4[3][0][d0.w], 1); g_srcs[0][p] = s0.w;
        p = atomicAdd(&g_cur4[0][1][d1.x], 1); g_srcs[1][p] = s1.x;
        p = atomicAdd(&g_cur4[1][1][d1.y], 1); g_srcs[1][p] = s1.y;
        p = atomicAdd(&g_cur4[2][1][d1.z], 1); g_srcs[1][p] = s1.z;
        p = atomicAdd(&g_cur4[3][1][d1.w], 1); g_srcs[1][p] = s1.w;
    } else {
        int n = t;
        int p0 = atomicAdd(&g_cur4[0][0][n], 1); g_srcs[0][p0] = n;
        int p1 = atomicAdd(&g_cur4[0][1][n], 1); g_srcs[1][p1] = n;
    }
}

// =======================================================================
// agg1 FUSED with projection: block per dst, 128 threads, BOTH relations.
// =======================================================================
__global__ void __launch_bounds__(128)
k_agg1proj(const __half* __restrict__ xp0, const __half* __restrict__ xp1,
           const float* __restrict__ att,
           const int* __restrict__ off, const int* __restrict__ srcs) {
    constexpr int CH = 512;
    __shared__ int   sh_src[CH];
    __shared__ float sh_e[2][CH];
    __shared__ float red[8];
    __shared__ float sh12[4][12];

    int dst = blockIdx.x, t = threadIdx.x;
    int lane = t & 31, w = t >> 5;
    int head = ((t * 4) >= C1) ? 1 : 0;

    float4 tot4 = make_float4(0.f, 0.f, 0.f, 0.f);

    #pragma unroll
    for (int rel = 0; rel < 2; rel++) {
        const __half* xp    = rel ? xp1 : xp0;
        const float*  alsr  = att + (rel * 2 + 0) * (NN * 2);
        const float*  aldr  = att + (rel * 2 + 1) * (NN * 2);
        const int*    offr  = off + (size_t)rel * (NN + 1);
        const int*    srcsr = srcs + (size_t)rel * E2;

        int o0 = offr[dst];
        int range = offr[dst + 1] - o0;
        float ad0 = aldr[dst * 2 + 0], ad1 = aldr[dst * 2 + 1];

        float sum0 = 0.f, sum1 = 0.f;
        float4 a4 = make_float4(0.f, 0.f, 0.f, 0.f);

        for (int base = 0; base < range; base += CH) {
            int nn = min(CH, range - base);
            __syncthreads();
            for (int i = t; i < nn; i += 128) {
                int s = srcsr[o0 + base + i];
                sh_src[i] = s;
                float l0 = alsr[s * 2 + 0] + ad0; l0 = l0 > 0.f ? l0 : 0.2f * l0;
                float l1 = alsr[s * 2 + 1] + ad1; l1 = l1 > 0.f ? l1 : 0.2f * l1;
                float e0 = expf(l0);
                float e1 = expf(l1);
                sh_e[0][i] = e0; sh_e[1][i] = e1;
                sum0 += e0; sum1 += e1;
            }
            __syncthreads();
            const float* eh = sh_e[head];
            #pragma unroll 4
            for (int j = 0; j < nn; j++) {
                int s = sh_src[j];
                float e = eh[j];
                uint2 v = ((const uint2*)(xp + (size_t)s * W1O))[t];
                __half2 h01 = *reinterpret_cast<__half2*>(&v.x);
                __half2 h23 = *reinterpret_cast<__half2*>(&v.y);
                float2 f01 = __half22float2(h01);
                float2 f23 = __half22float2(h23);
                a4.x = fmaf(e, f01.x, a4.x);
                a4.y = fmaf(e, f01.y, a4.y);
                a4.z = fmaf(e, f23.x, a4.z);
                a4.w = fmaf(e, f23.y, a4.w);
            }
        }
        #pragma unroll
        for (int o = 16; o; o >>= 1) {
            sum0 += __shfl_xor_sync(0xffffffffu, sum0, o);
            sum1 += __shfl_xor_sync(0xffffffffu, sum1, o);
        }
        if (lane == 0) { red[w] = sum0; red[4 + w] = sum1; }
        __syncthreads();
        sum0 = red[0] + red[1] + red[2] + red[3];
        sum1 = red[4] + red[5] + red[6] + red[7];
        float inv = head ? 1.f / (sum1 + 1e-16f) : 1.f / (sum0 + 1e-16f);
        tot4.x = fmaf(a4.x, inv, tot4.x);
        tot4.y = fmaf(a4.y, inv, tot4.y);
        tot4.z = fmaf(a4.z, inv, tot4.z);
        tot4.w = fmaf(a4.w, inv, tot4.w);
        __syncthreads();   // protect red before next relation
    }

    // h1 slice in registers: relu(tot4 + bb)
    float4 bv = ((const float4*)g_bb)[t];
    float4 hv;
    hv.x = tot4.x + bv.x; hv.x = hv.x > 0.f ? hv.x : 0.f;
    hv.y = tot4.y + bv.y; hv.y = hv.y > 0.f ? hv.y : 0.f;
    hv.z = tot4.z + bv.z; hv.z = hv.z > 0.f ? hv.z : 0.f;
    hv.w = tot4.w + bv.w; hv.w = hv.w > 0.f ? hv.w : 0.f;

    // 12 projection dots
    float p[12];
    const float4* V4 = (const float4*)g_V;   // [12][128] float4 rows
    #pragma unroll
    for (int v = 0; v < 12; v++) {
        float4 vv = V4[v * 128 + t];
        p[v] = hv.x * vv.x + hv.y * vv.y + hv.z * vv.z + hv.w * vv.w;
    }
    #pragma unroll
    for (int v = 0; v < 12; v++) {
        #pragma unroll
        for (int o = 16; o; o >>= 1) p[v] += __shfl_xor_sync(0xffffffffu, p[v], o);
    }
    if (lane == 0) {
        #pragma unroll
        for (int v = 0; v < 12; v++) sh12[w][v] = p[v];
    }
    __syncthreads();
    if (t < 12) {
        float r = sh12[0][t] + sh12[1][t] + sh12[2][t] + sh12[3][t];
        int rel = t >= 6;
        int vv = t % 6;
        g_l2[rel][vv >> 1][dst * 2 + (vv & 1)] = r;
    }
}

// =======================================================================
// agg2lite: WARP per (dst, rel); 256-thread blocks = 4 dsts x 2 rels.
// Pure warp-level: no __syncthreads, butterfly reductions only.
// =======================================================================
__global__ void __launch_bounds__(256)
k_agg2lite(const int* __restrict__ off, const int* __restrict__ srcs) {
    int t = threadIdx.x;
    int w = t >> 5, lane = t & 31;
    int dst = blockIdx.x * 4 + (w >> 1);
    int rel = w & 1;

    const float* als2 = g_l2[rel][0];
    const float* ald2 = g_l2[rel][1];
    const float* q2   = g_l2[rel][2];
    const int*   offr  = off + (size_t)rel * (NN + 1);
    const int*   srcsr = srcs + (size_t)rel * E2;

    int o0 = offr[dst];
    int range = offr[dst + 1] - o0;
    float ad0 = ald2[dst * 2 + 0], ad1 = ald2[dst * 2 + 1];

    float num0 = 0.f, num1 = 0.f, den0 = 0.f, den1 = 0.f;
    for (int i = lane; i < range; i += 32) {
        int s = srcsr[o0 + i];
        float2 al = ((const float2*)als2)[s];
        float2 qv = ((const float2*)q2)[s];
        float l0 = al.x + ad0; l0 = l0 > 0.f ? l0 : 0.2f * l0;
        float l1 = al.y + ad1; l1 = l1 > 0.f ? l1 : 0.2f * l1;
        float e0 = expf(l0);
        float e1 = expf(l1);
        den0 += e0; den1 += e1;
        num0 = fmaf(e0, qv.x, num0);
        num1 = fmaf(e1, qv.y, num1);
    }
    #pragma unroll
    for (int o = 16; o; o >>= 1) {
        num0 += __shfl_xor_sync(0xffffffffu, num0, o);
        num1 += __shfl_xor_sync(0xffffffffu, num1, o);
        den0 += __shfl_xor_sync(0xffffffffu, den0, o);
        den1 += __shfl_xor_sync(0xffffffffu, den1, o);
    }
    if (lane == 0)
        g_s2[rel][dst] = num0 / (den0 + 1e-16f) + num1 / (den1 + 1e-16f);
}

// ---------------- pairwise output: out[i*N+j] = s[i]+s[j]+2*cbias+b -------
__global__ void k_pair(float* __restrict__ out, const float* __restrict__ blin) {
    int idx = blockIdx.x * blockDim.x + threadIdx.x;
    float b = blin[0] + 2.f * g_cbias[0];
    int i = idx >> 8;
    int j4 = (idx & 255) << 2;
    float si = g_s2[0][i] + g_s2[1][i] + b;
    float4 v;
    v.x = si + g_s2[0][j4 + 0] + g_s2[1][j4 + 0];
    v.y = si + g_s2[0][j4 + 1] + g_s2[1][j4 + 1];
    v.z = si + g_s2[0][j4 + 2] + g_s2[1][j4 + 2];
    v.w = si + g_s2[0][j4 + 3] + g_s2[1][j4 + 3];
    ((float4*)out)[idx] = v;
}

// ---------------- launch ----------------
extern "C" void kernel_launch(void* const* d_in, const int* in_sizes, int n_in,
                              void* d_out, int out_size) {
    const float* x    = (const float*)d_in[0];
    const int*   ei0  = (const int*)d_in[1];
    const int*   ei1  = (const int*)d_in[2];
    const float* W1[2]  = {(const float*)d_in[3],  (const float*)d_in[7]};
    const float* as1[2] = {(const float*)d_in[4],  (const float*)d_in[8]};
    const float* ad1[2] = {(const float*)d_in[5],  (const float*)d_in[9]};
    const float* b1[2]  = {(const float*)d_in[6],  (const float*)d_in[10]};
    const float* W2[2]  = {(const float*)d_in[11], (const float*)d_in[15]};
    const float* as2[2] = {(const float*)d_in[12], (const float*)d_in[16]};
    const float* ad2[2] = {(const float*)d_in[13], (const float*)d_in[17]};
    const float* b2[2]  = {(const float*)d_in[14], (const float*)d_in[18]};
    const float* wlin = (const float*)d_in[19];
    const float* blin = (const float*)d_in[20];
    float* out = (float*)d_out;

    float *attp;
    __half* xph;
    int *cnt4p, *offp, *srcsp;
    cudaGetSymbolAddress((void**)&xph,   g_xph);
    cudaGetSymbolAddress((void**)&attp,  g_att);
    cudaGetSymbolAddress((void**)&cnt4p, g_cnt4);
    cudaGetSymbolAddress((void**)&offp,  g_off);
    cudaGetSymbolAddress((void**)&srcsp, g_srcs);

    __half* xph0 = xph;
    __half* xph1 = xph + (size_t)NN * W1O;

    cudaMemsetAsync(cnt4p, 0, 4 * 2 * NN * sizeof(int));
    cudaMemsetAsync(attp, 0, 2 * 2 * NN * 2 * sizeof(float));

    // gemm1 (fp16 out, +attn1 epilogue) + sharded count + layer-2 prep
    k_gemm1_count<<<G1_GEMM_BLOCKS + G1_COUNT_BLOCKS + G1_PREP_BLOCKS, 256>>>(
        x, W1[0], W1[1], xph0, xph1, ei0, ei1,
        as1[0], as1[1], ad1[0], ad1[1], attp,
        W2[0], W2[1], as2[0], as2[1], ad2[0], ad2[1], wlin);

    // fused scan + fill
    k_scanfill<<<2 + SF_FILL_BLOCKS, 1024>>>(
        ei0, ei1, b1[0], b1[1], b2[0], b2[1], wlin);

    // layer-1 aggregation fused with layer-2 projection
    k_agg1proj<<<NN, 128>>>(xph0, xph1, attp, offp, srcsp);

    // layer-2 scalar aggregation (warp per dst-rel)
    k_agg2lite<<<NN / 4, 256>>>(offp, srcsp);

    k_pair<<<NN * NN / 4 / 256, 256>>>(out, blin);
}

// round 16
// speedup vs baseline: 1.0359x; 1.0359x over previous
#include <cuda_runtime.h>
#include <cuda_fp16.h>

#define DEV_INLINE __device__ __forceinline__

constexpr int NN   = 1024;
constexpr int EE   = 65536;
constexpr int E2   = EE + NN;      // edges + self loops
constexpr int W1O  = 512;          // H*256
constexpr int C1   = 256;
constexpr int W2O  = 128;          // H*64
constexpr int C2   = 64;

// ---------------- scratch (device globals) -------------
__device__ __half g_xph[2][NN * W1O];   // layer-1 projected features (fp16)
__device__ float  g_bb[W1O];            // b1_0+b1_1
__device__ float  g_cbias[1];           // sum((b2_0+b2_1)*wlin)
__device__ float  g_att[2 * 2 * NN * 2];// layer1 [rel][als/ald][node*2+head]
__device__ float  g_V[2][6][W1O];       // W2_r @ {as2_h0,as2_h1,ad2_h0,ad2_h1,wl_h0,wl_h1}
__device__ float  g_l2[2][3][NN * 2];   // [rel][als2/ald2/q][node*2+head]
__device__ int    g_cnt4s[4 * 2 * NN + 2]; // sharded counts + 2 sync flags (zeroed together)
__device__ int    g_cur4[4][2][NN];     // sharded fill cursors
__device__ int    g_off[2][NN + 1];
__device__ int    g_srcs[2][E2];
__device__ float  g_s2[2][NN];          // per-relation score partials

// =======================================================================
// MEGA-FUSED launch 1:
//   [0,128)      gemm1 (both relations, fp16 out) + attn1 logit epilogue
//   [128,192)    sharded edge count   -> sync0++
//   [192,196)    layer-2 projection-vector prep
//   [196,198)    CSR scan (256 thr, 4 nodes/thr), spins sync0==64 -> sync1++
//   [198,262)    CSR edge fill (int4), spins sync1==2
//   [262,266)    CSR self-loop fill,   spins sync1==2
// =======================================================================
constexpr int G1_GEMM_BLOCKS  = 128;
constexpr int G1_COUNT_BLOCKS = 64;
constexpr int G1_PREP_BLOCKS  = 4;
constexpr int G1_SCAN_BLOCKS  = 2;
constexpr int G1_FILL_BLOCKS  = 64;
constexpr int G1_SELF_BLOCKS  = 4;
constexpr int G1_TOTAL = G1_GEMM_BLOCKS + G1_COUNT_BLOCKS + G1_PREP_BLOCKS +
                         G1_SCAN_BLOCKS + G1_FILL_BLOCKS + G1_SELF_BLOCKS;  // 266

DEV_INLINE int cnt4_at(int shard, int rel, int node) {
    return (shard * 2 + rel) * NN + node;
}

__global__ void __launch_bounds__(256)
k_mega(const float* __restrict__ A,
       const float* __restrict__ B0, const float* __restrict__ B1,
       __half* __restrict__ Ch0, __half* __restrict__ Ch1,
       const int* __restrict__ ei0, const int* __restrict__ ei1,
       const float* __restrict__ as0, const float* __restrict__ as1,
       const float* __restrict__ ad0, const float* __restrict__ ad1,
       float* __restrict__ att,
       const float* __restrict__ W2_0, const float* __restrict__ W2_1,
       const float* __restrict__ as2_0, const float* __restrict__ as2_1,
       const float* __restrict__ ad2_0, const float* __restrict__ ad2_1,
       const float* __restrict__ wlin,
       const float* __restrict__ b1_0, const float* __restrict__ b1_1,
       const float* __restrict__ b2_0, const float* __restrict__ b2_1) {
    int bid = blockIdx.x;
    int t = threadIdx.x;
    int* sync = g_cnt4s + 8 * NN;

    // ---------------- count blocks ----------------
    if (bid >= G1_GEMM_BLOCKS && bid < G1_GEMM_BLOCKS + G1_COUNT_BLOCKS) {
        int cid = bid - G1_GEMM_BLOCKS;
        int idx = cid * 256 + t;
        int4 d0 = ((const int4*)(ei0 + EE))[idx];
        int4 d1 = ((const int4*)(ei1 + EE))[idx];
        atomicAdd(&g_cnt4s[cnt4_at(0, 0, d0.x)], 1);
        atomicAdd(&g_cnt4s[cnt4_at(1, 0, d0.y)], 1);
        atomicAdd(&g_cnt4s[cnt4_at(2, 0, d0.z)], 1);
        atomicAdd(&g_cnt4s[cnt4_at(3, 0, d0.w)], 1);
        atomicAdd(&g_cnt4s[cnt4_at(0, 1, d1.x)], 1);
        atomicAdd(&g_cnt4s[cnt4_at(1, 1, d1.y)], 1);
        atomicAdd(&g_cnt4s[cnt4_at(2, 1, d1.z)], 1);
        atomicAdd(&g_cnt4s[cnt4_at(3, 1, d1.w)], 1);
        __threadfence();
        __syncthreads();
        if (t == 0) atomicAdd(&sync[0], 1);
        return;
    }

    // ---------------- prep blocks (V vectors) ----------------
    if (bid >= G1_GEMM_BLOCKS + G1_COUNT_BLOCKS &&
        bid <  G1_GEMM_BLOCKS + G1_COUNT_BLOCKS + G1_PREP_BLOCKS) {
        int pb  = bid - (G1_GEMM_BLOCKS + G1_COUNT_BLOCKS);   // 0..3
        int rel = pb >> 1, half = pb & 1;
        int k = half * 256 + t;
        const float* W2r = rel ? W2_1 : W2_0;
        const float* a2  = rel ? as2_1 : as2_0;
        const float* d2  = rel ? ad2_1 : ad2_0;
        const float* row = W2r + (size_t)k * W2O;
        float s_[6] = {0.f, 0.f, 0.f, 0.f, 0.f, 0.f};
        #pragma unroll 8
        for (int c = 0; c < 64; c++) {
            float w0 = row[c], w1 = row[64 + c];
            s_[0] = fmaf(w0, a2[c],        s_[0]);
            s_[1] = fmaf(w1, a2[64 + c],   s_[1]);
            s_[2] = fmaf(w0, d2[c],        s_[2]);
            s_[3] = fmaf(w1, d2[64 + c],   s_[3]);
            s_[4] = fmaf(w0, wlin[c],      s_[4]);
            s_[5] = fmaf(w1, wlin[64 + c], s_[5]);
        }
        #pragma unroll
        for (int v = 0; v < 6; v++) g_V[rel][v][k] = s_[v];
        return;
    }

    // ---------------- scan blocks ----------------
    if (bid >= G1_GEMM_BLOCKS + G1_COUNT_BLOCKS + G1_PREP_BLOCKS &&
        bid <  G1_GEMM_BLOCKS + G1_COUNT_BLOCKS + G1_PREP_BLOCKS + G1_SCAN_BLOCKS) {
        int r = bid - (G1_GEMM_BLOCKS + G1_COUNT_BLOCKS + G1_PREP_BLOCKS);
        __shared__ int sh[256];
        __shared__ float fred[4];

        if (t == 0) {
            while (atomicAdd(&sync[0], 0) < G1_COUNT_BLOCKS) {}
        }
        __syncthreads();
        __threadfence();

        // 4 nodes per thread
        int c[4][4], tot[4];
        int lsum = 0;
        #pragma unroll
        for (int u = 0; u < 4; u++) {
            int node = t * 4 + u;
            c[u][0] = g_cnt4s[cnt4_at(0, r, node)] + 1;   // self loop in shard 0
            c[u][1] = g_cnt4s[cnt4_at(1, r, node)];
            c[u][2] = g_cnt4s[cnt4_at(2, r, node)];
            c[u][3] = g_cnt4s[cnt4_at(3, r, node)];
            tot[u] = c[u][0] + c[u][1] + c[u][2] + c[u][3];
            lsum += tot[u];
        }
        sh[t] = lsum;
        __syncthreads();
        #pragma unroll
        for (int d = 1; d < 256; d <<= 1) {
            int v = (t >= d) ? sh[t - d] : 0;
            __syncthreads();
            sh[t] += v;
            __syncthreads();
        }
        int base = sh[t] - lsum;   // exclusive prefix for this thread's group
        if (t == 0) g_off[r][0] = 0;
        #pragma unroll
        for (int u = 0; u < 4; u++) {
            int node = t * 4 + u;
            g_off[r][node + 1] = base + tot[u];
            g_cur4[0][r][node] = base;
            g_cur4[1][r][node] = base + c[u][0];
            g_cur4[2][r][node] = base + c[u][0] + c[u][1];
            g_cur4[3][r][node] = base + c[u][0] + c[u][1] + c[u][2];
            base += tot[u];
        }

        // side duties
        if (r == 0) {
            g_bb[t]       = b1_0[t] + b1_1[t];
            g_bb[t + 256] = b1_0[t + 256] + b1_1[t + 256];
        } else {
            float p = 0.f;
            if (t < W2O) p = (b2_0[t] + b2_1[t]) * wlin[t];
            if (t < 128) {
                #pragma unroll
                for (int o = 16; o; o >>= 1) p += __shfl_xor_sync(0xffffffffu, p, o);
                if ((t & 31) == 0) fred[t >> 5] = p;
            }
            __syncthreads();
            if (t == 0) g_cbias[0] = fred[0] + fred[1] + fred[2] + fred[3];
        }

        __threadfence();
        __syncthreads();
        if (t == 0) atomicAdd(&sync[1], 1);
        return;
    }

    // ---------------- fill blocks ----------------
    if (bid >= G1_GEMM_BLOCKS + G1_COUNT_BLOCKS + G1_PREP_BLOCKS + G1_SCAN_BLOCKS) {
        int fb = bid - (G1_GEMM_BLOCKS + G1_COUNT_BLOCKS + G1_PREP_BLOCKS + G1_SCAN_BLOCKS);
        if (t == 0) {
            while (atomicAdd(&sync[1], 0) < G1_SCAN_BLOCKS) {}
        }
        __syncthreads();
        __threadfence();

        if (fb < G1_FILL_BLOCKS) {
            int idx = fb * 256 + t;     // int4 index; 64*256 = EE/4
            int4 s0 = ((const int4*)ei0)[idx];
            int4 d0 = ((const int4*)(ei0 + EE))[idx];
            int4 s1 = ((const int4*)ei1)[idx];
            int4 d1 = ((const int4*)(ei1 + EE))[idx];
            int p;
            p = atomicAdd(&g_cur4[0][0][d0.x], 1); g_srcs[0][p] = s0.x;
            p = atomicAdd(&g_cur4[1][0][d0.y], 1); g_srcs[0][p] = s0.y;
            p = atomicAdd(&g_cur4[2][0][d0.z], 1); g_srcs[0][p] = s0.z;
            p = atomicAdd(&g_cur4[3][0][d0.w], 1); g_srcs[0][p] = s0.w;
            p = atomicAdd(&g_cur4[0][1][d1.x], 1); g_srcs[1][p] = s1.x;
            p = atomicAdd(&g_cur4[1][1][d1.y], 1); g_srcs[1][p] = s1.y;
            p = atomicAdd(&g_cur4[2][1][d1.z], 1); g_srcs[1][p] = s1.z;
            p = atomicAdd(&g_cur4[3][1][d1.w], 1); g_srcs[1][p] = s1.w;
        } else {
            int n = (fb - G1_FILL_BLOCKS) * 256 + t;   // self loops
            int p0 = atomicAdd(&g_cur4[0][0][n], 1); g_srcs[0][p0] = n;
            int p1 = atomicAdd(&g_cur4[0][1][n], 1); g_srcs[1][p1] = n;
        }
        return;
    }

    // ---------------- gemm blocks ----------------
    constexpr int K = 256, Nc = W1O;
    __shared__ float4 sh[768];
    float*  As  = (float*)sh;
    float4* As4 = sh;                            // row stride 32
    float4* Bs4 = sh + 512;                      // [16][16]

    int rel = bid >> 6;
    int r   = bid & 63;
    int bn  = (r & 7) * 64;
    int bm  = (r >> 3) * 128;
    const float* B = rel ? B1 : B0;
    __half*      Ch = rel ? Ch1 : Ch0;

    int tx = t & 15, ty = t >> 4;
    int am = t >> 2, ak = (t & 3) * 4;

    float4 acc[8];
    #pragma unroll
    for (int i = 0; i < 8; i++) acc[i] = make_float4(0.f, 0.f, 0.f, 0.f);

    float4 a_reg0 = *(const float4*)(A + (size_t)(bm + am) * K + ak);
    float4 a_reg1 = *(const float4*)(A + (size_t)(bm + am + 64) * K + ak);
    float4 b_reg  = *(const float4*)(B + (size_t)(t >> 4) * Nc + bn + (t & 15) * 4);

    for (int k0 = 0; k0 < K; k0 += 16) {
        As[(ak + 0) * 128 + am] = a_reg0.x;
        As[(ak + 1) * 128 + am] = a_reg0.y;
        As[(ak + 2) * 128 + am] = a_reg0.z;
        As[(ak + 3) * 128 + am] = a_reg0.w;
        As[(ak + 0) * 128 + am + 64] = a_reg1.x;
        As[(ak + 1) * 128 + am + 64] = a_reg1.y;
        As[(ak + 2) * 128 + am + 64] = a_reg1.z;
        As[(ak + 3) * 128 + am + 64] = a_reg1.w;
        Bs4[(t >> 4) * 16 + (t & 15)] = b_reg;
        __syncthreads();

        if (k0 + 16 < K) {
            a_reg0 = *(const float4*)(A + (size_t)(bm + am) * K + k0 + 16 + ak);
            a_reg1 = *(const float4*)(A + (size_t)(bm + am + 64) * K + k0 + 16 + ak);
            b_reg  = *(const float4*)(B + (size_t)(k0 + 16 + (t >> 4)) * Nc + bn + (t & 15) * 4);
        }

        #pragma unroll
        for (int k = 0; k < 16; k++) {
            float4 a0 = As4[k * 32 + ty * 2];
            float4 a1 = As4[k * 32 + ty * 2 + 1];
            float4 b  = Bs4[k * 16 + tx];
            float ar[8] = {a0.x, a0.y, a0.z, a0.w, a1.x, a1.y, a1.z, a1.w};
            #pragma unroll
            for (int i = 0; i < 8; i++) {
                acc[i].x = fmaf(ar[i], b.x, acc[i].x);
                acc[i].y = fmaf(ar[i], b.y, acc[i].y);
                acc[i].z = fmaf(ar[i], b.z, acc[i].z);
                acc[i].w = fmaf(ar[i], b.w, acc[i].w);
            }
        }
        __syncthreads();
    }
    #pragma unroll
    for (int i = 0; i < 8; i++) {
        __half2 h01 = __floats2half2_rn(acc[i].x, acc[i].y);
        __half2 h23 = __floats2half2_rn(acc[i].z, acc[i].w);
        uint2 v;
        v.x = *reinterpret_cast<unsigned*>(&h01);
        v.y = *reinterpret_cast<unsigned*>(&h23);
        ((uint2*)(Ch + (size_t)(bm + ty * 8 + i) * Nc))[(bn >> 2) + tx] = v;
    }

    // fused attn1 logit partials
    const float* asrc = rel ? as1 : as0;
    const float* adst = rel ? ad1 : ad0;
    int h   = bn >> 8;
    int cin = (bn & 255) + tx * 4;
    float4 avs = *(const float4*)(asrc + h * C1 + cin);
    float4 avd = *(const float4*)(adst + h * C1 + cin);
    float* alsb = att + (rel * 2 + 0) * (NN * 2);
    float* aldb = att + (rel * 2 + 1) * (NN * 2);
    #pragma unroll
    for (int i = 0; i < 8; i++) {
        float ps = acc[i].x * avs.x + acc[i].y * avs.y + acc[i].z * avs.z + acc[i].w * avs.w;
        float pd = acc[i].x * avd.x + acc[i].y * avd.y + acc[i].z * avd.z + acc[i].w * avd.w;
        #pragma unroll
        for (int o = 8; o; o >>= 1) {
            ps += __shfl_xor_sync(0xffffffffu, ps, o);
            pd += __shfl_xor_sync(0xffffffffu, pd, o);
        }
        if (tx == 0) {
            int row = bm + ty * 8 + i;
            atomicAdd(&alsb[row * 2 + h], ps);
            atomicAdd(&aldb[row * 2 + h], pd);
        }
    }
}

// =======================================================================
// agg1 FUSED with projection: block per dst, 128 threads, BOTH relations.
// =======================================================================
__global__ void __launch_bounds__(128)
k_agg1proj(const __half* __restrict__ xp0, const __half* __restrict__ xp1,
           const float* __restrict__ att,
           const int* __restrict__ off, const int* __restrict__ srcs) {
    constexpr int CH = 512;
    __shared__ int   sh_src[CH];
    __shared__ float sh_e[2][CH];
    __shared__ float red[8];
    __shared__ float sh12[4][12];

    int dst = blockIdx.x, t = threadIdx.x;
    int lane = t & 31, w = t >> 5;
    int head = ((t * 4) >= C1) ? 1 : 0;

    float4 tot4 = make_float4(0.f, 0.f, 0.f, 0.f);

    #pragma unroll
    for (int rel = 0; rel < 2; rel++) {
        const __half* xp    = rel ? xp1 : xp0;
        const float*  alsr  = att + (rel * 2 + 0) * (NN * 2);
        const float*  aldr  = att + (rel * 2 + 1) * (NN * 2);
        const int*    offr  = off + (size_t)rel * (NN + 1);
        const int*    srcsr = srcs + (size_t)rel * E2;

        int o0 = offr[dst];
        int range = offr[dst + 1] - o0;
        float ad0 = aldr[dst * 2 + 0], ad1 = aldr[dst * 2 + 1];

        float sum0 = 0.f, sum1 = 0.f;
        float4 a4 = make_float4(0.f, 0.f, 0.f, 0.f);

        for (int base = 0; base < range; base += CH) {
            int nn = min(CH, range - base);
            __syncthreads();
            for (int i = t; i < nn; i += 128) {
                int s = srcsr[o0 + base + i];
                sh_src[i] = s;
                float l0 = alsr[s * 2 + 0] + ad0; l0 = l0 > 0.f ? l0 : 0.2f * l0;
                float l1 = alsr[s * 2 + 1] + ad1; l1 = l1 > 0.f ? l1 : 0.2f * l1;
                float e0 = expf(l0);
                float e1 = expf(l1);
                sh_e[0][i] = e0; sh_e[1][i] = e1;
                sum0 += e0; sum1 += e1;
            }
            __syncthreads();
            const float* eh = sh_e[head];
            #pragma unroll 4
            for (int j = 0; j < nn; j++) {
                int s = sh_src[j];
                float e = eh[j];
                uint2 v = ((const uint2*)(xp + (size_t)s * W1O))[t];
                __half2 h01 = *reinterpret_cast<__half2*>(&v.x);
                __half2 h23 = *reinterpret_cast<__half2*>(&v.y);
                float2 f01 = __half22float2(h01);
                float2 f23 = __half22float2(h23);
                a4.x = fmaf(e, f01.x, a4.x);
                a4.y = fmaf(e, f01.y, a4.y);
                a4.z = fmaf(e, f23.x, a4.z);
                a4.w = fmaf(e, f23.y, a4.w);
            }
        }
        #pragma unroll
        for (int o = 16; o; o >>= 1) {
            sum0 += __shfl_xor_sync(0xffffffffu, sum0, o);
            sum1 += __shfl_xor_sync(0xffffffffu, sum1, o);
        }
        if (lane == 0) { red[w] = sum0; red[4 + w] = sum1; }
        __syncthreads();
        sum0 = red[0] + red[1] + red[2] + red[3];
        sum1 = red[4] + red[5] + red[6] + red[7];
        float inv = head ? 1.f / (sum1 + 1e-16f) : 1.f / (sum0 + 1e-16f);
        tot4.x = fmaf(a4.x, inv, tot4.x);
        tot4.y = fmaf(a4.y, inv, tot4.y);
        tot4.z = fmaf(a4.z, inv, tot4.z);
        tot4.w = fmaf(a4.w, inv, tot4.w);
        __syncthreads();   // protect red before next relation
    }

    // h1 slice in registers: relu(tot4 + bb)
    float4 bv = ((const float4*)g_bb)[t];
    float4 hv;
    hv.x = tot4.x + bv.x; hv.x = hv.x > 0.f ? hv.x : 0.f;
    hv.y = tot4.y + bv.y; hv.y = hv.y > 0.f ? hv.y : 0.f;
    hv.z = tot4.z + bv.z; hv.z = hv.z > 0.f ? hv.z : 0.f;
    hv.w = tot4.w + bv.w; hv.w = hv.w > 0.f ? hv.w : 0.f;

    // 12 projection dots
    float p[12];
    const float4* V4 = (const float4*)g_V;   // [12][128] float4 rows
    #pragma unroll
    for (int v = 0; v < 12; v++) {
        float4 vv = V4[v * 128 + t];
        p[v] = hv.x * vv.x + hv.y * vv.y + hv.z * vv.z + hv.w * vv.w;
    }
    #pragma unroll
    for (int v = 0; v < 12; v++) {
        #pragma unroll
        for (int o = 16; o; o >>= 1) p[v] += __shfl_xor_sync(0xffffffffu, p[v], o);
    }
    if (lane == 0) {
        #pragma unroll
        for (int v = 0; v < 12; v++) sh12[w][v] = p[v];
    }
    __syncthreads();
    if (t < 12) {
        float r = sh12[0][t] + sh12[1][t] + sh12[2][t] + sh12[3][t];
        int rel = t >= 6;
        int vv = t % 6;
        g_l2[rel][vv >> 1][dst * 2 + (vv & 1)] = r;
    }
}

// =======================================================================
// agg2lite: block per (dst, rel), 64 threads (round-14 measured shape)
// =======================================================================
__global__ void __launch_bounds__(64)
k_agg2lite(const int* __restrict__ off, const int* __restrict__ srcs) {
    __shared__ float red[8];
    int dst = blockIdx.x, rel = blockIdx.y, t = threadIdx.x;
    int lane = t & 31, w = t >> 5;

    const float* als2 = g_l2[rel][0];
    const float* ald2 = g_l2[rel][1];
    const float* q2   = g_l2[rel][2];
    const int*   offr  = off + (size_t)rel * (NN + 1);
    const int*   srcsr = srcs + (size_t)rel * E2;

    int o0 = offr[dst];
    int range = offr[dst + 1] - o0;
    float ad0 = ald2[dst * 2 + 0], ad1 = ald2[dst * 2 + 1];

    float num0 = 0.f, num1 = 0.f, den0 = 0.f, den1 = 0.f;
    for (int i = t; i < range; i += 64) {
        int s = srcsr[o0 + i];
        float2 al = ((const float2*)als2)[s];
        float2 qv = ((const float2*)q2)[s];
        float l0 = al.x + ad0; l0 = l0 > 0.f ? l0 : 0.2f * l0;
        float l1 = al.y + ad1; l1 = l1 > 0.f ? l1 : 0.2f * l1;
        float e0 = expf(l0);
        float e1 = expf(l1);
        den0 += e0; den1 += e1;
        num0 = fmaf(e0, qv.x, num0);
        num1 = fmaf(e1, qv.y, num1);
    }
    #pragma unroll
    for (int o = 16; o; o >>= 1) {
        num0 += __shfl_xor_sync(0xffffffffu, num0, o);
        num1 += __shfl_xor_sync(0xffffffffu, num1, o);
        den0 += __shfl_xor_sync(0xffffffffu, den0, o);
        den1 += __shfl_xor_sync(0xffffffffu, den1, o);
    }
    if (lane == 0) {
        red[w * 4 + 0] = num0; red[w * 4 + 1] = num1;
        red[w * 4 + 2] = den0; red[w * 4 + 3] = den1;
    }
    __syncthreads();
    if (t == 0) {
        float n0 = red[0] + red[4], n1 = red[1] + red[5];
        float d0 = red[2] + red[6], d1 = red[3] + red[7];
        g_s2[rel][dst] = n0 / (d0 + 1e-16f) + n1 / (d1 + 1e-16f);
    }
}

// ---------------- pairwise output: out[i*N+j] = s[i]+s[j]+2*cbias+b -------
__global__ void k_pair(float* __restrict__ out, const float* __restrict__ blin) {
    int idx = blockIdx.x * blockDim.x + threadIdx.x;
    float b = blin[0] + 2.f * g_cbias[0];
    int i = idx >> 8;
    int j4 = (idx & 255) << 2;
    float si = g_s2[0][i] + g_s2[1][i] + b;
    float4 v;
    v.x = si + g_s2[0][j4 + 0] + g_s2[1][j4 + 0];
    v.y = si + g_s2[0][j4 + 1] + g_s2[1][j4 + 1];
    v.z = si + g_s2[0][j4 + 2] + g_s2[1][j4 + 2];
    v.w = si + g_s2[0][j4 + 3] + g_s2[1][j4 + 3];
    ((float4*)out)[idx] = v;
}

// ---------------- launch ----------------
extern "C" void kernel_launch(void* const* d_in, const int* in_sizes, int n_in,
                              void* d_out, int out_size) {
    const float* x    = (const float*)d_in[0];
    const int*   ei0  = (const int*)d_in[1];
    const int*   ei1  = (const int*)d_in[2];
    const float* W1[2]  = {(const float*)d_in[3],  (const float*)d_in[7]};
    const float* as1[2] = {(const float*)d_in[4],  (const float*)d_in[8]};
    const float* ad1[2] = {(const float*)d_in[5],  (const float*)d_in[9]};
    const float* b1[2]  = {(const float*)d_in[6],  (const float*)d_in[10]};
    const float* W2[2]  = {(const float*)d_in[11], (const float*)d_in[15]};
    const float* as2[2] = {(const float*)d_in[12], (const float*)d_in[16]};
    const float* ad2[2] = {(const float*)d_in[13], (const float*)d_in[17]};
    const float* b2[2]  = {(const float*)d_in[14], (const float*)d_in[18]};
    const float* wlin = (const float*)d_in[19];
    const float* blin = (const float*)d_in[20];
    float* out = (float*)d_out;

    float *attp;
    __half* xph;
    int *cnt4sp, *offp, *srcsp;
    cudaGetSymbolAddress((void**)&xph,    g_xph);
    cudaGetSymbolAddress((void**)&attp,   g_att);
    cudaGetSymbolAddress((void**)&cnt4sp, g_cnt4s);
    cudaGetSymbolAddress((void**)&offp,   g_off);
    cudaGetSymbolAddress((void**)&srcsp,  g_srcs);

    __half* xph0 = xph;
    __half* xph1 = xph + (size_t)NN * W1O;

    cudaMemsetAsync(cnt4sp, 0, (4 * 2 * NN + 2) * sizeof(int));
    cudaMemsetAsync(attp, 0, 2 * 2 * NN * 2 * sizeof(float));

    // mega launch: gemm1 + count + prep + scan + fill (flag-ordered)
    k_mega<<<G1_TOTAL, 256>>>(
        x, W1[0], W1[1], xph0, xph1, ei0, ei1,
        as1[0], as1[1], ad1[0], ad1[1], attp,
        W2[0], W2[1], as2[0], as2[1], ad2[0], ad2[1], wlin,
        b1[0], b1[1], b2[0], b2[1]);

    // layer-1 aggregation fused with layer-2 projection
    k_agg1proj<<<NN, 128>>>(xph0, xph1, attp, offp, srcsp);

    // layer-2 scalar aggregation
    k_agg2lite<<<dim3(NN, 2), 64>>>(offp, srcsp);

    k_pair<<<NN * NN / 4 / 256, 256>>>(out, blin);
}